// round 1
// baseline (speedup 1.0000x reference)
#include <cuda_runtime.h>

#define NN   5000
#define TT   12
#define DAYC 8
#define FF   7
#define DIMC 96
#define MAX_NZ 512

// Scratch (allocation-free rule: __device__ globals)
__device__ float g_agg[NN * DIMC];   // [n][j], j = t*8+d, pre-scaled by 1/deg
__device__ float g_feat[NN * DIMC];  // his: col t*7+i ; cur: col 84+t

// ---------------------------------------------------------------------------
// Kernel 1: per-row normalized aggregation  agg[n][t*8+d] = (1/deg) * sum_{adj[n,i]=1} data[t,i,d]
// One warp per row. Deterministic ballot-based nonzero compaction (no atomics).
// ---------------------------------------------------------------------------
__global__ void __launch_bounds__(128) agg_kernel(const float* __restrict__ adj,
                                                  const float* __restrict__ data) {
    __shared__ int s_nz[4][MAX_NZ];
    const int w    = threadIdx.x >> 5;
    const int lane = threadIdx.x & 31;
    const int row  = blockIdx.x * 4 + w;

    const float4* __restrict__ arow =
        reinterpret_cast<const float4*>(adj + (long long)row * NN);
    int cnt = 0;
    const int NV4 = NN / 4;  // 1250
    for (int base = 0; base < NV4; base += 32) {
        const int i4 = base + lane;
        float4 v = make_float4(0.f, 0.f, 0.f, 0.f);
        if (i4 < NV4) v = arow[i4];
        #pragma unroll
        for (int s = 0; s < 4; s++) {
            const float vs = (s == 0) ? v.x : ((s == 1) ? v.y : ((s == 2) ? v.z : v.w));
            const unsigned m = __ballot_sync(0xffffffffu, vs != 0.0f);
            if (vs != 0.0f) {
                const int p = cnt + __popc(m & ((1u << lane) - 1u));
                if (p < MAX_NZ) s_nz[w][p] = i4 * 4 + s;
            }
            cnt += __popc(m);
        }
    }
    __syncwarp();
    const int nnz = (cnt < MAX_NZ) ? cnt : MAX_NZ;
    const float scale = 1.0f / (float)((cnt > 0) ? cnt : 1);

    // Each lane owns output cols lane, lane+32, lane+64
    const int j0 = lane, j1 = lane + 32, j2 = lane + 64;
    const int o0 = (j0 >> 3) * (NN * DAYC) + (j0 & 7);
    const int o1 = (j1 >> 3) * (NN * DAYC) + (j1 & 7);
    const int o2 = (j2 >> 3) * (NN * DAYC) + (j2 & 7);
    float a0 = 0.f, a1 = 0.f, a2 = 0.f;
    for (int k = 0; k < nnz; k++) {
        const int b = s_nz[w][k] * DAYC;
        a0 += __ldg(data + o0 + b);   // adj value is exactly 1.0 -> pure sum
        a1 += __ldg(data + o1 + b);
        a2 += __ldg(data + o2 + b);
    }
    g_agg[row * DIMC + j0] = a0 * scale;
    g_agg[row * DIMC + j1] = a1 * scale;
    g_agg[row * DIMC + j2] = a2 * scale;
}

// ---------------------------------------------------------------------------
// Kernel 2: per-node sequential recurrence (thread per node).
// his_prev/cur_prev recurrences use running accumulators (history never materialized).
// ---------------------------------------------------------------------------
__global__ void __launch_bounds__(64) rec_kernel(const float* __restrict__ data,
                                                 const float* __restrict__ pos,
                                                 const float* __restrict__ hisW,   // (12,7,28)
                                                 const float* __restrict__ curW,   // (12,1,4)
                                                 const float* __restrict__ hw,     // (7,95)
                                                 const float* __restrict__ cw) {   // (1,12)
    __shared__ float s_hisW[TT * FF * 28];  // 2352
    __shared__ float s_curW[TT * 4];        // 48
    __shared__ float s_hw[FF * 95];         // 665
    __shared__ float s_cw[TT];              // 12
    for (int i = threadIdx.x; i < TT * FF * 28; i += 64) s_hisW[i] = hisW[i];
    for (int i = threadIdx.x; i < TT * 4;       i += 64) s_curW[i] = curW[i];
    for (int i = threadIdx.x; i < FF * 95;      i += 64) s_hw[i]   = hw[i];
    if (threadIdx.x < TT) s_cw[threadIdx.x] = cw[threadIdx.x];
    __syncthreads();

    const int n = blockIdx.x * 64 + threadIdx.x;
    if (n >= NN) return;

    float accH[FF]  = {0.f, 0.f, 0.f, 0.f, 0.f, 0.f, 0.f};
    float prevH[FF] = {0.f, 0.f, 0.f, 0.f, 0.f, 0.f, 0.f};
    float accC = 0.f, prevC = 0.f;

    for (int t = 0; t < TT; t++) {
        const float4* dp = reinterpret_cast<const float4*>(data  + ((long long)t * NN + n) * DAYC);
        const float4* pp = reinterpret_cast<const float4*>(pos   + ((long long)t * NN + n) * DAYC);
        const float4* ap = reinterpret_cast<const float4*>(g_agg + n * DIMC + t * DAYC);
        const float4 d0 = dp[0], d1 = dp[1];
        const float4 p0 = pp[0], p1 = pp[1];
        const float4 g0 = ap[0], g1 = ap[1];
        const float raw[8] = {d0.x, d0.y, d0.z, d0.w, d1.x, d1.y, d1.z, d1.w};
        const float pv[8]  = {p0.x, p0.y, p0.z, p0.w, p1.x, p1.y, p1.z, p1.w};
        const float ag[8]  = {g0.x, g0.y, g0.z, g0.w, g1.x, g1.y, g1.z, g1.w};

        // his GNN: combined = [raw(7), agg(7), zeros(7), prevH(7)] @ W^T, relu, +pos
        float h[FF];
        const float* Wt = s_hisW + t * FF * 28;
        #pragma unroll
        for (int i = 0; i < FF; i++) {
            const float* Wr = Wt + i * 28;
            float s = 0.f;
            #pragma unroll
            for (int j = 0; j < FF; j++) {
                s += raw[j]   * Wr[j];
                s += ag[j]    * Wr[7 + j];
                s += prevH[j] * Wr[21 + j];
            }
            h[i] = fmaxf(s, 0.f) + pv[i];
        }
        // cur GNN: [raw(1), agg(1), 0, prevC] @ curW[t]^T
        float c = raw[7] * s_curW[t * 4 + 0] + ag[7] * s_curW[t * 4 + 1]
                + prevC * s_curW[t * 4 + 3];
        c = fmaxf(c, 0.f) + pv[7];

        // his_prev = relu(running sum of h_s @ hw[:, s*7:(s+1)*7]^T)
        #pragma unroll
        for (int i = 0; i < FF; i++) {
            float s = 0.f;
            #pragma unroll
            for (int j = 0; j < FF; j++) s += h[j] * s_hw[i * 95 + t * FF + j];
            accH[i] += s;
            prevH[i] = fmaxf(accH[i], 0.f);
        }
        accC += c * s_cw[t];
        prevC = fmaxf(accC, 0.f);

        #pragma unroll
        for (int i = 0; i < FF; i++) g_feat[n * DIMC + t * FF + i] = h[i];
        g_feat[n * DIMC + TT * FF + t] = c;
    }
}

// ---------------------------------------------------------------------------
// Kernel 3: out = relu(feat @ FW^T). Warp per node, FW^T staged in shared
// (conflict-free: lane-major columns), 32 nodes per block.
// ---------------------------------------------------------------------------
__global__ void __launch_bounds__(128) final_kernel(const float* __restrict__ FW,
                                                    float* __restrict__ out) {
    __shared__ float s_FWt[DIMC * DIMC];  // s_FWt[k*96 + j] = FW[j*96 + k]
    __shared__ float s_feat[4][DIMC];
    for (int i = threadIdx.x; i < DIMC * DIMC; i += 128) {
        const int j = i / DIMC, k = i % DIMC;
        s_FWt[k * DIMC + j] = FW[i];
    }
    __syncthreads();

    const int w = threadIdx.x >> 5, lane = threadIdx.x & 31;
    #pragma unroll 1
    for (int it = 0; it < 8; it++) {
        const int n = blockIdx.x * 32 + it * 4 + w;
        if (n < NN) {
            s_feat[w][lane]      = g_feat[n * DIMC + lane];
            s_feat[w][lane + 32] = g_feat[n * DIMC + lane + 32];
            s_feat[w][lane + 64] = g_feat[n * DIMC + lane + 64];
            __syncwarp();
            float a0 = 0.f, a1 = 0.f, a2 = 0.f;
            #pragma unroll 8
            for (int k = 0; k < DIMC; k++) {
                const float fv = s_feat[w][k];
                a0 += fv * s_FWt[k * DIMC + lane];
                a1 += fv * s_FWt[k * DIMC + lane + 32];
                a2 += fv * s_FWt[k * DIMC + lane + 64];
            }
            out[n * DIMC + lane]      = fmaxf(a0, 0.f);
            out[n * DIMC + lane + 32] = fmaxf(a1, 0.f);
            out[n * DIMC + lane + 64] = fmaxf(a2, 0.f);
            __syncwarp();
        }
    }
}

// ---------------------------------------------------------------------------
extern "C" void kernel_launch(void* const* d_in, const int* in_sizes, int n_in,
                              void* d_out, int out_size) {
    const float* adj  = (const float*)d_in[0];
    const float* data = (const float*)d_in[1];
    const float* pos  = (const float*)d_in[2];
    const float* hisW = (const float*)d_in[3];
    const float* curW = (const float*)d_in[4];
    const float* hw   = (const float*)d_in[5];
    const float* cw   = (const float*)d_in[6];
    const float* fw   = (const float*)d_in[7];
    float* out = (float*)d_out;

    agg_kernel<<<NN / 4, 128>>>(adj, data);
    rec_kernel<<<(NN + 63) / 64, 64>>>(data, pos, hisW, curW, hw, cw);
    final_kernel<<<(NN + 31) / 32, 128>>>(fw, out);
}

// round 3
// speedup vs baseline: 1.3552x; 1.3552x over previous
#include <cuda_runtime.h>

#define NN   5000
#define TT   12
#define DAYC 8
#define FF   7
#define DIMC 96
#define MAX_NZ 128   // max row degree; Binomial(5000,0.005): mean 25, 128 is >15 sigma

// Scratch (allocation-free rule: __device__ globals)
__device__ float g_agg[NN * DIMC];   // [n][j], j = t*8+d, pre-scaled by 1/deg
__device__ float g_feat[NN * DIMC];  // his: col t*7+i ; cur: col 84+t

// ---------------------------------------------------------------------------
// Kernel 1: agg[n][t*8+d] = (1/deg_n) * sum_{adj[n,i]!=0} data[t,i,d]
// One warp per row. 4-deep pipelined float4 scan (MLP=4), deterministic
// ballot compaction, then warp-wide gather (lane owns 3 output cols).
// ---------------------------------------------------------------------------
__global__ void __launch_bounds__(128) agg_kernel(const float* __restrict__ adj,
                                                  const float* __restrict__ data) {
    __shared__ int s_nz[4][MAX_NZ];
    const int w    = threadIdx.x >> 5;
    const int lane = threadIdx.x & 31;
    const int row  = blockIdx.x * 4 + w;

    const float4* __restrict__ arow =
        reinterpret_cast<const float4*>(adj + (long long)row * NN);
    const int NV4 = NN / 4;  // 1250
    int cnt = 0;

    for (int base = 0; base < NV4; base += 128) {
        // batch 4 independent loads first (MLP=4)
        float4 v[4];
        #pragma unroll
        for (int u = 0; u < 4; u++) {
            const int i4 = base + u * 32 + lane;
            v[u] = make_float4(0.f, 0.f, 0.f, 0.f);
            if (i4 < NV4) v[u] = __ldg(&arow[i4]);
        }
        // then process ballots
        #pragma unroll
        for (int u = 0; u < 4; u++) {
            const int i4 = base + u * 32 + lane;
            #pragma unroll
            for (int s = 0; s < 4; s++) {
                const float vs = (s == 0) ? v[u].x : ((s == 1) ? v[u].y
                               : ((s == 2) ? v[u].z : v[u].w));
                const unsigned m = __ballot_sync(0xffffffffu, vs != 0.0f);
                if (vs != 0.0f) {
                    const int p = cnt + __popc(m & ((1u << lane) - 1u));
                    if (p < MAX_NZ) s_nz[w][p] = i4 * 4 + s;
                }
                cnt += __popc(m);
            }
        }
    }
    __syncwarp();
    const int nnz = (cnt < MAX_NZ) ? cnt : MAX_NZ;
    const float scale = 1.0f / (float)((cnt > 0) ? cnt : 1);

    // lane owns output cols lane, lane+32, lane+64
    const int j0 = lane, j1 = lane + 32, j2 = lane + 64;
    const int o0 = (j0 >> 3) * (NN * DAYC) + (j0 & 7);
    const int o1 = (j1 >> 3) * (NN * DAYC) + (j1 & 7);
    const int o2 = (j2 >> 3) * (NN * DAYC) + (j2 & 7);
    float a0 = 0.f, a1 = 0.f, a2 = 0.f;
    for (int k = 0; k < nnz; k++) {
        const int b = s_nz[w][k] * DAYC;
        a0 += __ldg(data + o0 + b);   // adj nonzeros are exactly 1.0 -> pure sum
        a1 += __ldg(data + o1 + b);
        a2 += __ldg(data + o2 + b);
    }
    g_agg[row * DIMC + j0] = a0 * scale;
    g_agg[row * DIMC + j1] = a1 * scale;
    g_agg[row * DIMC + j2] = a2 * scale;
}

// ---------------------------------------------------------------------------
// Kernel 2: per-node recurrence, 8 lanes per node (lane li<7 owns channel li,
// lane 7 owns the "cur" scalar channel). 256 threads = 32 nodes per block.
// his/cur recurrences use running accumulators (history never materialized).
// ---------------------------------------------------------------------------
__global__ void __launch_bounds__(256) rec_kernel(const float* __restrict__ data,
                                                  const float* __restrict__ pos,
                                                  const float* __restrict__ hisW,   // (12,7,28)
                                                  const float* __restrict__ curW,   // (12,1,4)
                                                  const float* __restrict__ hw,     // (7,95)
                                                  const float* __restrict__ cw) {   // (1,12)
    __shared__ float s_hisW[TT * FF * 28];  // 2352
    __shared__ float s_curW[TT * 4];        // 48
    __shared__ float s_hw[FF * 95];         // 665
    __shared__ float s_cw[TT];              // 12
    __shared__ float s_raw[32][8], s_ag[32][8], s_prev[32][8], s_h[32][8];

    for (int i = threadIdx.x; i < TT * FF * 28; i += 256) s_hisW[i] = hisW[i];
    for (int i = threadIdx.x; i < TT * 4;       i += 256) s_curW[i] = curW[i];
    for (int i = threadIdx.x; i < FF * 95;      i += 256) s_hw[i]   = hw[i];
    if (threadIdx.x < TT) s_cw[threadIdx.x] = cw[threadIdx.x];

    const int warp = threadIdx.x >> 5;
    const int lane = threadIdx.x & 31;
    const int sub  = lane >> 3;         // node within warp (0..3)
    const int li   = lane & 7;          // channel role (0..7)
    const int nl   = warp * 4 + sub;    // node within block (0..31)
    const int n    = blockIdx.x * 32 + nl;
    const bool act = (n < NN);
    const int  nc  = act ? n : 0;       // clamped for loads

    s_prev[nl][li] = 0.f;               // prevH init
    __syncthreads();                    // weights + prev visible

    float accH = 0.f;                   // lane li: accH[li]
    float accC = 0.f, prevC = 0.f;      // lane 7 only

    for (int t = 0; t < TT; t++) {
        const long long base = ((long long)t * NN + nc) * DAYC + li;
        const float rawv = __ldg(data + base);
        const float pvv  = __ldg(pos  + base);
        const float agv  = g_agg[nc * DIMC + t * DAYC + li];

        s_raw[nl][li] = rawv;
        s_ag[nl][li]  = agv;
        __syncwarp();

        float hv;
        if (li < 7) {
            // h[li] = relu( raw·W[li][0:7] + agg·W[li][7:14] + prevH·W[li][21:28] ) + pos[li]
            const float* Wr = s_hisW + t * FF * 28 + li * 28;
            float s = 0.f;
            #pragma unroll
            for (int j = 0; j < FF; j++) {
                s += s_raw[nl][j]  * Wr[j];
                s += s_ag[nl][j]   * Wr[7 + j];
                s += s_prev[nl][j] * Wr[21 + j];
            }
            hv = fmaxf(s, 0.f) + pvv;
        } else {
            // cur channel: c = relu(raw7*w0 + agg7*w1 + prevC*w3) + pos7
            float c = rawv * s_curW[t * 4 + 0] + agv * s_curW[t * 4 + 1]
                    + prevC * s_curW[t * 4 + 3];
            hv = fmaxf(c, 0.f) + pvv;
        }
        s_h[nl][li] = hv;
        __syncwarp();

        if (li < 7) {
            // his_prev[li] = relu( running_sum += h_t · hw[li][t*7 : t*7+7] )
            const float* hr = s_hw + li * 95 + t * FF;
            float s = 0.f;
            #pragma unroll
            for (int j = 0; j < FF; j++) s += s_h[nl][j] * hr[j];
            accH += s;
            s_prev[nl][li] = fmaxf(accH, 0.f);
            if (act) g_feat[n * DIMC + t * FF + li] = hv;
        } else {
            accC += hv * s_cw[t];
            prevC = fmaxf(accC, 0.f);
            if (act) g_feat[n * DIMC + TT * FF + t] = hv;
        }
    }
}

// ---------------------------------------------------------------------------
// Kernel 3: out = relu(feat @ FW^T). Block = 128 threads / 16 nodes.
// FW^T in shared (pad 97 -> conflict-free transpose store and load),
// feat tile in shared; each lane holds a 4-node x 3-col register tile.
// Static smem: 96*97*4 + 16*96*4 = 43392 B (< 48 KB limit).
// ---------------------------------------------------------------------------
__global__ void __launch_bounds__(128) final_kernel(const float* __restrict__ FW,
                                                    float* __restrict__ out) {
    __shared__ float s_FWt[DIMC * 97];     // s_FWt[k*97 + j] = FW[j*96 + k]
    __shared__ float s_feat[16][DIMC];
    const int tid = threadIdx.x;
    const int nb  = blockIdx.x * 16;

    for (int i = tid; i < DIMC * DIMC; i += 128) {
        const int j = i / DIMC, k = i % DIMC;
        s_FWt[k * 97 + j] = FW[i];
    }
    for (int i = tid; i < 16 * DIMC; i += 128) {
        const int nl = i / DIMC, k = i % DIMC;
        const int n = nb + nl;
        s_feat[nl][k] = (n < NN) ? g_feat[n * DIMC + k] : 0.f;
    }
    __syncthreads();

    const int w = tid >> 5, lane = tid & 31;
    const int nl0 = w * 4;                 // 4 warps x 4 nodes = 16 nodes
    float acc[4][3];
    #pragma unroll
    for (int m = 0; m < 4; m++) { acc[m][0] = acc[m][1] = acc[m][2] = 0.f; }

    #pragma unroll 4
    for (int k = 0; k < DIMC; k++) {
        const float f0 = s_FWt[k * 97 + lane];
        const float f1 = s_FWt[k * 97 + lane + 32];
        const float f2 = s_FWt[k * 97 + lane + 64];
        #pragma unroll
        for (int m = 0; m < 4; m++) {
            const float fv = s_feat[nl0 + m][k];   // broadcast within warp
            acc[m][0] += fv * f0;
            acc[m][1] += fv * f1;
            acc[m][2] += fv * f2;
        }
    }
    #pragma unroll
    for (int m = 0; m < 4; m++) {
        const int n = nb + nl0 + m;
        if (n < NN) {
            out[n * DIMC + lane]      = fmaxf(acc[m][0], 0.f);
            out[n * DIMC + lane + 32] = fmaxf(acc[m][1], 0.f);
            out[n * DIMC + lane + 64] = fmaxf(acc[m][2], 0.f);
        }
    }
}

// ---------------------------------------------------------------------------
extern "C" void kernel_launch(void* const* d_in, const int* in_sizes, int n_in,
                              void* d_out, int out_size) {
    const float* adj  = (const float*)d_in[0];
    const float* data = (const float*)d_in[1];
    const float* pos  = (const float*)d_in[2];
    const float* hisW = (const float*)d_in[3];
    const float* curW = (const float*)d_in[4];
    const float* hw   = (const float*)d_in[5];
    const float* cw   = (const float*)d_in[6];
    const float* fw   = (const float*)d_in[7];
    float* out = (float*)d_out;

    agg_kernel<<<NN / 4, 128>>>(adj, data);
    rec_kernel<<<(NN + 31) / 32, 256>>>(data, pos, hisW, curW, hw, cw);
    final_kernel<<<(NN + 15) / 16, 128>>>(fw, out);
}

// round 4
// speedup vs baseline: 1.4019x; 1.0345x over previous
#include <cuda_runtime.h>

#define NN   5000
#define TT   12
#define DAYC 8
#define FF   7
#define DIMC 96
#define NV4  1250         // NN/4
#define QW   313          // float4s per quarter-row scan (ceil 1250/4)
#define QNZ  64           // max nonzeros per quarter-row (mean ~6.3, >>15 sigma)

// Scratch (allocation-free rule: __device__ globals)
__device__ float g_agg[NN * DIMC];   // [n][j], j = t*8+d, pre-scaled by 1/deg
__device__ float g_feat[NN * DIMC];  // his: col t*7+i ; cur: col 84+t

// ---------------------------------------------------------------------------
// Kernel 1: agg[n][t*8+d] = (1/deg_n) * sum_{adj[n,i]!=0} data[t,i,d]
// 4 warps per row (quarter scans) -> full occupancy. 256 thr = 2 rows/block.
// Per-warp ballot compaction (deterministic), per-warp gather partials,
// warp 0 of each row reduces the 4 partials and scales by 1/deg.
// ---------------------------------------------------------------------------
__global__ void __launch_bounds__(256) agg_kernel(const float* __restrict__ adj,
                                                  const float* __restrict__ data) {
    __shared__ int   s_nz[2][4][QNZ];
    __shared__ int   s_cnt[2][4];
    __shared__ float s_part[2][4][DIMC];

    const int warp = threadIdx.x >> 5;
    const int lane = threadIdx.x & 31;
    const int r    = warp >> 2;           // row slot in block (0..1)
    const int q    = warp & 3;            // quarter (0..3)
    const int row  = blockIdx.x * 2 + r;

    const float4* __restrict__ arow =
        reinterpret_cast<const float4*>(adj + (long long)row * NN);
    const int i4beg = q * QW;
    const int i4end = (i4beg + QW < NV4) ? (i4beg + QW) : NV4;

    int cnt = 0;
    for (int base = i4beg; base < i4end; base += 128) {
        float4 v[4];
        #pragma unroll
        for (int u = 0; u < 4; u++) {
            const int i4 = base + u * 32 + lane;
            v[u] = make_float4(0.f, 0.f, 0.f, 0.f);
            if (i4 < i4end) v[u] = __ldg(&arow[i4]);
        }
        #pragma unroll
        for (int u = 0; u < 4; u++) {
            const int i4 = base + u * 32 + lane;
            #pragma unroll
            for (int s = 0; s < 4; s++) {
                const float vs = (s == 0) ? v[u].x : ((s == 1) ? v[u].y
                               : ((s == 2) ? v[u].z : v[u].w));
                const unsigned m = __ballot_sync(0xffffffffu, vs != 0.0f);
                if (vs != 0.0f) {
                    const int p = cnt + __popc(m & ((1u << lane) - 1u));
                    if (p < QNZ) s_nz[r][q][p] = i4 * 4 + s;
                }
                cnt += __popc(m);
            }
        }
    }
    if (lane == 0) s_cnt[r][q] = cnt;
    __syncwarp();
    const int nnz = (cnt < QNZ) ? cnt : QNZ;

    // gather own list: lane owns output cols lane, lane+32, lane+64
    const int j0 = lane, j1 = lane + 32, j2 = lane + 64;
    const int o0 = (j0 >> 3) * (NN * DAYC) + (j0 & 7);
    const int o1 = (j1 >> 3) * (NN * DAYC) + (j1 & 7);
    const int o2 = (j2 >> 3) * (NN * DAYC) + (j2 & 7);
    float a0 = 0.f, a1 = 0.f, a2 = 0.f;
    #pragma unroll 2
    for (int k = 0; k < nnz; k++) {
        const int b = s_nz[r][q][k] * DAYC;   // adj nonzeros are exactly 1.0
        a0 += __ldg(data + o0 + b);
        a1 += __ldg(data + o1 + b);
        a2 += __ldg(data + o2 + b);
    }
    s_part[r][q][j0] = a0;
    s_part[r][q][j1] = a1;
    s_part[r][q][j2] = a2;
    __syncthreads();

    if (q == 0) {
        const int tot = s_cnt[r][0] + s_cnt[r][1] + s_cnt[r][2] + s_cnt[r][3];
        const float scale = 1.0f / (float)((tot > 0) ? tot : 1);
        #pragma unroll
        for (int c3 = 0; c3 < 3; c3++) {
            const int c = lane + c3 * 32;
            g_agg[row * DIMC + c] = (s_part[r][0][c] + s_part[r][1][c]
                                   + s_part[r][2][c] + s_part[r][3][c]) * scale;
        }
    }
}

// ---------------------------------------------------------------------------
// Kernel 2: per-node recurrence, 8 lanes per node (lane li<7 owns channel li,
// lane 7 owns the "cur" scalar). 256 threads = 32 nodes per block.
// ALL 36 global values (data/pos/agg x 12t) prefetched to registers up front
// so only one memory latency is exposed (grid is tiny: 157 blocks).
// ---------------------------------------------------------------------------
__global__ void __launch_bounds__(256) rec_kernel(const float* __restrict__ data,
                                                  const float* __restrict__ pos,
                                                  const float* __restrict__ hisW,   // (12,7,28)
                                                  const float* __restrict__ curW,   // (12,1,4)
                                                  const float* __restrict__ hw,     // (7,95)
                                                  const float* __restrict__ cw) {   // (1,12)
    __shared__ float s_hisW[TT * FF * 28];  // 2352
    __shared__ float s_curW[TT * 4];        // 48
    __shared__ float s_hw[FF * 95];         // 665
    __shared__ float s_cw[TT];              // 12
    __shared__ float s_raw[32][8], s_ag[32][8], s_prev[32][8], s_h[32][8];

    for (int i = threadIdx.x; i < TT * FF * 28; i += 256) s_hisW[i] = hisW[i];
    for (int i = threadIdx.x; i < TT * 4;       i += 256) s_curW[i] = curW[i];
    for (int i = threadIdx.x; i < FF * 95;      i += 256) s_hw[i]   = hw[i];
    if (threadIdx.x < TT) s_cw[threadIdx.x] = cw[threadIdx.x];

    const int warp = threadIdx.x >> 5;
    const int lane = threadIdx.x & 31;
    const int sub  = lane >> 3;         // node within warp (0..3)
    const int li   = lane & 7;          // channel role (0..7)
    const int nl   = warp * 4 + sub;    // node within block (0..31)
    const int n    = blockIdx.x * 32 + nl;
    const bool act = (n < NN);
    const int  nc  = act ? n : 0;       // clamped for loads

    // prefetch everything (36 independent loads in flight)
    float rawv[TT], pvv[TT], agv[TT];
    #pragma unroll
    for (int t = 0; t < TT; t++) {
        const long long base = ((long long)t * NN + nc) * DAYC + li;
        rawv[t] = __ldg(data + base);
        pvv[t]  = __ldg(pos  + base);
        agv[t]  = g_agg[nc * DIMC + t * DAYC + li];
    }

    s_prev[nl][li] = 0.f;               // prevH init
    __syncthreads();                    // weights + prev visible

    float accH = 0.f;                   // lane li: accH[li]
    float accC = 0.f, prevC = 0.f;      // lane 7 only

    #pragma unroll
    for (int t = 0; t < TT; t++) {
        s_raw[nl][li] = rawv[t];
        s_ag[nl][li]  = agv[t];
        __syncwarp();

        float hv;
        if (li < 7) {
            // h[li] = relu( raw·W[li][0:7] + agg·W[li][7:14] + prevH·W[li][21:28] ) + pos[li]
            const float* Wr = s_hisW + t * FF * 28 + li * 28;
            float s = 0.f;
            #pragma unroll
            for (int j = 0; j < FF; j++) {
                s += s_raw[nl][j]  * Wr[j];
                s += s_ag[nl][j]   * Wr[7 + j];
                s += s_prev[nl][j] * Wr[21 + j];
            }
            hv = fmaxf(s, 0.f) + pvv[t];
        } else {
            float c = rawv[t] * s_curW[t * 4 + 0] + agv[t] * s_curW[t * 4 + 1]
                    + prevC * s_curW[t * 4 + 3];
            hv = fmaxf(c, 0.f) + pvv[t];
        }
        s_h[nl][li] = hv;
        __syncwarp();

        if (li < 7) {
            const float* hr = s_hw + li * 95 + t * FF;
            float s = 0.f;
            #pragma unroll
            for (int j = 0; j < FF; j++) s += s_h[nl][j] * hr[j];
            accH += s;
            s_prev[nl][li] = fmaxf(accH, 0.f);
            if (act) g_feat[n * DIMC + t * FF + li] = hv;
        } else {
            accC += hv * s_cw[t];
            prevC = fmaxf(accC, 0.f);
            if (act) g_feat[n * DIMC + TT * FF + t] = hv;
        }
    }
}

// ---------------------------------------------------------------------------
// Kernel 3: out = relu(feat @ FW^T). Block = 128 threads / 16 nodes.
// FW^T in shared (pad 97, conflict-free), 4-node x 3-col register tile/lane.
// Static smem: 96*97*4 + 16*96*4 = 43392 B (< 48 KB limit).
// ---------------------------------------------------------------------------
__global__ void __launch_bounds__(128) final_kernel(const float* __restrict__ FW,
                                                    float* __restrict__ out) {
    __shared__ float s_FWt[DIMC * 97];     // s_FWt[k*97 + j] = FW[j*96 + k]
    __shared__ float s_feat[16][DIMC];
    const int tid = threadIdx.x;
    const int nb  = blockIdx.x * 16;

    for (int i = tid; i < DIMC * DIMC; i += 128) {
        const int j = i / DIMC, k = i % DIMC;
        s_FWt[k * 97 + j] = FW[i];
    }
    for (int i = tid; i < 16 * DIMC; i += 128) {
        const int nl = i / DIMC, k = i % DIMC;
        const int n = nb + nl;
        s_feat[nl][k] = (n < NN) ? g_feat[n * DIMC + k] : 0.f;
    }
    __syncthreads();

    const int w = tid >> 5, lane = tid & 31;
    const int nl0 = w * 4;                 // 4 warps x 4 nodes = 16 nodes
    float acc[4][3];
    #pragma unroll
    for (int m = 0; m < 4; m++) { acc[m][0] = acc[m][1] = acc[m][2] = 0.f; }

    #pragma unroll 4
    for (int k = 0; k < DIMC; k++) {
        const float f0 = s_FWt[k * 97 + lane];
        const float f1 = s_FWt[k * 97 + lane + 32];
        const float f2 = s_FWt[k * 97 + lane + 64];
        #pragma unroll
        for (int m = 0; m < 4; m++) {
            const float fv = s_feat[nl0 + m][k];   // broadcast within warp
            acc[m][0] += fv * f0;
            acc[m][1] += fv * f1;
            acc[m][2] += fv * f2;
        }
    }
    #pragma unroll
    for (int m = 0; m < 4; m++) {
        const int n = nb + nl0 + m;
        if (n < NN) {
            out[n * DIMC + lane]      = fmaxf(acc[m][0], 0.f);
            out[n * DIMC + lane + 32] = fmaxf(acc[m][1], 0.f);
            out[n * DIMC + lane + 64] = fmaxf(acc[m][2], 0.f);
        }
    }
}

// ---------------------------------------------------------------------------
extern "C" void kernel_launch(void* const* d_in, const int* in_sizes, int n_in,
                              void* d_out, int out_size) {
    const float* adj  = (const float*)d_in[0];
    const float* data = (const float*)d_in[1];
    const float* pos  = (const float*)d_in[2];
    const float* hisW = (const float*)d_in[3];
    const float* curW = (const float*)d_in[4];
    const float* hw   = (const float*)d_in[5];
    const float* cw   = (const float*)d_in[6];
    const float* fw   = (const float*)d_in[7];
    float* out = (float*)d_out;

    agg_kernel<<<NN / 2, 256>>>(adj, data);
    rec_kernel<<<(NN + 31) / 32, 256>>>(data, pos, hisW, curW, hw, cw);
    final_kernel<<<(NN + 15) / 16, 128>>>(fw, out);
}

// round 5
// speedup vs baseline: 1.6263x; 1.1600x over previous
#include <cuda_runtime.h>

#define NN   5000
#define TT   12
#define DAYC 8
#define FF   7
#define DIMC 96
#define NV4  1250         // float4s per adj row
#define QW   313          // float4s per quarter-row scan (ceil 1250/4)
#define QNZ  64           // max nonzero-records per quarter (mean ~6.2)

// Scratch (allocation-free rule: __device__ global)
__device__ float g_agg[NN * DIMC];   // [n][t*8+d], pre-scaled by 1/deg

// ---------------------------------------------------------------------------
// Kernel 1: agg[n][t*8+d] = (1/deg_n) * sum_{adj[n,i]!=0} data[t,i,d]
// 4 warps per row (quarter scans), 256 thr = 2 rows/block.
// Scan: integer-OR nonzero test, ONE ballot per float4, records (i4<<4)|mask.
// Gather decodes bit masks; degree = sum popc(mask).
// ---------------------------------------------------------------------------
__global__ void __launch_bounds__(256) agg_kernel(const float* __restrict__ adj,
                                                  const float* __restrict__ data) {
    __shared__ int   s_nz[2][4][QNZ];
    __shared__ int   s_cnt[2][4];
    __shared__ float s_part[2][4][DIMC];

    const int warp = threadIdx.x >> 5;
    const int lane = threadIdx.x & 31;
    const int r    = warp >> 2;           // row slot in block (0..1)
    const int q    = warp & 3;            // quarter (0..3)
    const int row  = blockIdx.x * 2 + r;
    const unsigned lt = (1u << lane) - 1u;

    const uint4* __restrict__ arow =
        reinterpret_cast<const uint4*>(adj + (long long)row * NN);
    const int i4beg = q * QW;
    const int i4end = (i4beg + QW < NV4) ? (i4beg + QW) : NV4;

    int cnt = 0;  // record count
    for (int base = i4beg; base < i4end; base += 128) {
        uint4 v[4];
        #pragma unroll
        for (int u = 0; u < 4; u++) {
            const int i4 = base + u * 32 + lane;
            v[u] = make_uint4(0u, 0u, 0u, 0u);
            if (i4 < i4end) v[u] = __ldg(&arow[i4]);
        }
        #pragma unroll
        for (int u = 0; u < 4; u++) {
            const int i4 = base + u * 32 + lane;
            const unsigned any = v[u].x | v[u].y | v[u].z | v[u].w;
            const unsigned m = __ballot_sync(0xffffffffu, any != 0u);
            if (any != 0u) {
                const unsigned mask = (v[u].x ? 1u : 0u) | (v[u].y ? 2u : 0u)
                                    | (v[u].z ? 4u : 0u) | (v[u].w ? 8u : 0u);
                const int p = cnt + __popc(m & lt);
                if (p < QNZ) s_nz[r][q][p] = (i4 << 4) | (int)mask;
            }
            cnt += __popc(m);
        }
    }
    __syncwarp();
    const int nrec = (cnt < QNZ) ? cnt : QNZ;

    // gather: lane owns output cols lane, lane+32, lane+64
    const int j0 = lane, j1 = lane + 32, j2 = lane + 64;
    const int o0 = (j0 >> 3) * (NN * DAYC) + (j0 & 7);
    const int o1 = (j1 >> 3) * (NN * DAYC) + (j1 & 7);
    const int o2 = (j2 >> 3) * (NN * DAYC) + (j2 & 7);
    float a0 = 0.f, a1 = 0.f, a2 = 0.f;
    int deg = 0;
    for (int k = 0; k < nrec; k++) {
        const int rec = s_nz[r][q][k];
        const int eb = (rec >> 4) * 4;
        unsigned mk = (unsigned)(rec & 15);
        deg += __popc(mk);
        do {
            const int b = __ffs(mk) - 1;
            mk &= mk - 1u;
            const int off = (eb + b) * DAYC;   // adj nonzeros are exactly 1.0
            a0 += __ldg(data + o0 + off);
            a1 += __ldg(data + o1 + off);
            a2 += __ldg(data + o2 + off);
        } while (mk);
    }
    s_part[r][q][j0] = a0;
    s_part[r][q][j1] = a1;
    s_part[r][q][j2] = a2;
    if (lane == 0) s_cnt[r][q] = deg;
    __syncthreads();

    if (q == 0) {
        const int tot = s_cnt[r][0] + s_cnt[r][1] + s_cnt[r][2] + s_cnt[r][3];
        const float scale = 1.0f / (float)((tot > 0) ? tot : 1);
        #pragma unroll
        for (int c3 = 0; c3 < 3; c3++) {
            const int c = lane + c3 * 32;
            g_agg[row * DIMC + c] = (s_part[r][0][c] + s_part[r][1][c]
                                   + s_part[r][2][c] + s_part[r][3][c]) * scale;
        }
    }
}

// ---------------------------------------------------------------------------
// Kernel 2 (fused rec + final): 256 threads = 32 nodes per block.
// Rec: 8 lanes per node (lane li<7 owns his-channel li, lane 7 the cur scalar);
// feats kept in shared. Final: warp w reads the SAME 4 nodes it produced
// (nl = w*4..w*4+3) -> only __syncwarp between phases. FW^T staged once per
// block in dynamic shared (pad 97, conflict-free).
// ---------------------------------------------------------------------------
__global__ void __launch_bounds__(256) recfinal_kernel(const float* __restrict__ data,
                                                       const float* __restrict__ pos,
                                                       const float* __restrict__ hisW,   // (12,7,28)
                                                       const float* __restrict__ curW,   // (12,1,4)
                                                       const float* __restrict__ hw,     // (7,95)
                                                       const float* __restrict__ cw,     // (1,12)
                                                       const float* __restrict__ FW,     // (96,96)
                                                       float* __restrict__ out) {
    extern __shared__ float sm[];
    float* s_hisW = sm;                    // 2352
    float* s_curW = s_hisW + TT * FF * 28; // 48
    float* s_hw   = s_curW + TT * 4;       // 665
    float* s_cw   = s_hw + FF * 95;        // 12
    float* s_raw  = s_cw + TT;             // 32*8
    float* s_ag   = s_raw + 256;           // 32*8
    float* s_prev = s_ag + 256;            // 32*8
    float* s_h    = s_prev + 256;          // 32*8
    float* s_feat = s_h + 256;             // 32*96
    float* s_FWt  = s_feat + 32 * DIMC;    // 96*97

    const int tid = threadIdx.x;
    for (int i = tid; i < TT * FF * 28; i += 256) s_hisW[i] = hisW[i];
    for (int i = tid; i < TT * 4;       i += 256) s_curW[i] = curW[i];
    for (int i = tid; i < FF * 95;      i += 256) s_hw[i]   = hw[i];
    if (tid < TT) s_cw[tid] = cw[tid];
    for (int i = tid; i < DIMC * DIMC; i += 256) {
        const int j = i / DIMC, k = i - j * DIMC;
        s_FWt[k * 97 + j] = FW[i];         // transpose, pad-97: conflict-free
    }

    const int warp = tid >> 5;
    const int lane = tid & 31;
    const int sub  = lane >> 3;           // node within warp (0..3)
    const int li   = lane & 7;            // channel role (0..7)
    const int nl   = warp * 4 + sub;      // node within block (0..31)
    const int n    = blockIdx.x * 32 + nl;
    const bool act = (n < NN);
    const int  nc  = act ? n : 0;

    // prefetch all per-node inputs (36 independent loads in flight)
    float rawv[TT], pvv[TT], agv[TT];
    #pragma unroll
    for (int t = 0; t < TT; t++) {
        const long long base = ((long long)t * NN + nc) * DAYC + li;
        rawv[t] = __ldg(data + base);
        pvv[t]  = __ldg(pos  + base);
        agv[t]  = g_agg[nc * DIMC + t * DAYC + li];
    }

    s_prev[nl * 8 + li] = 0.f;
    __syncthreads();                       // weights + FWt + prev visible

    float accH = 0.f;                      // lane li: accH[li]
    float accC = 0.f, prevC = 0.f;         // lane 7 only

    #pragma unroll
    for (int t = 0; t < TT; t++) {
        s_raw[nl * 8 + li] = rawv[t];
        s_ag[nl * 8 + li]  = agv[t];
        __syncwarp();

        float hv;
        if (li < 7) {
            const float* Wr = s_hisW + t * FF * 28 + li * 28;
            float s = 0.f;
            #pragma unroll
            for (int j = 0; j < FF; j++) {
                s += s_raw[nl * 8 + j]  * Wr[j];
                s += s_ag[nl * 8 + j]   * Wr[7 + j];
                s += s_prev[nl * 8 + j] * Wr[21 + j];
            }
            hv = fmaxf(s, 0.f) + pvv[t];
        } else {
            float c = rawv[t] * s_curW[t * 4 + 0] + agv[t] * s_curW[t * 4 + 1]
                    + prevC * s_curW[t * 4 + 3];
            hv = fmaxf(c, 0.f) + pvv[t];
        }
        s_h[nl * 8 + li] = hv;
        __syncwarp();

        if (li < 7) {
            const float* hr = s_hw + li * 95 + t * FF;
            float s = 0.f;
            #pragma unroll
            for (int j = 0; j < FF; j++) s += s_h[nl * 8 + j] * hr[j];
            accH += s;
            s_prev[nl * 8 + li] = fmaxf(accH, 0.f);
            s_feat[nl * DIMC + t * FF + li] = hv;
        } else {
            accC += hv * s_cw[t];
            prevC = fmaxf(accC, 0.f);
            s_feat[nl * DIMC + TT * FF + t] = hv;
        }
    }
    __syncwarp();   // warp w's feats (nodes w*4..w*4+3) visible to warp w

    // ---- final: out[n] = relu(feat[n] @ FW^T) for this warp's 4 nodes ----
    const int nl0 = warp * 4;
    float acc[4][3];
    #pragma unroll
    for (int m = 0; m < 4; m++) { acc[m][0] = acc[m][1] = acc[m][2] = 0.f; }

    #pragma unroll 4
    for (int k = 0; k < DIMC; k++) {
        const float f0 = s_FWt[k * 97 + lane];
        const float f1 = s_FWt[k * 97 + lane + 32];
        const float f2 = s_FWt[k * 97 + lane + 64];
        #pragma unroll
        for (int m = 0; m < 4; m++) {
            const float fv = s_feat[(nl0 + m) * DIMC + k];  // broadcast
            acc[m][0] += fv * f0;
            acc[m][1] += fv * f1;
            acc[m][2] += fv * f2;
        }
    }
    #pragma unroll
    for (int m = 0; m < 4; m++) {
        const int nn = blockIdx.x * 32 + nl0 + m;
        if (nn < NN) {
            out[nn * DIMC + lane]      = fmaxf(acc[m][0], 0.f);
            out[nn * DIMC + lane + 32] = fmaxf(acc[m][1], 0.f);
            out[nn * DIMC + lane + 64] = fmaxf(acc[m][2], 0.f);
        }
    }
}

// ---------------------------------------------------------------------------
#define RECFINAL_SMEM ((TT*FF*28 + TT*4 + FF*95 + TT + 4*256 + 32*DIMC + DIMC*97) * (int)sizeof(float))

extern "C" void kernel_launch(void* const* d_in, const int* in_sizes, int n_in,
                              void* d_out, int out_size) {
    const float* adj  = (const float*)d_in[0];
    const float* data = (const float*)d_in[1];
    const float* pos  = (const float*)d_in[2];
    const float* hisW = (const float*)d_in[3];
    const float* curW = (const float*)d_in[4];
    const float* hw   = (const float*)d_in[5];
    const float* cw   = (const float*)d_in[6];
    const float* fw   = (const float*)d_in[7];
    float* out = (float*)d_out;

    cudaFuncSetAttribute(recfinal_kernel,
                         cudaFuncAttributeMaxDynamicSharedMemorySize,
                         RECFINAL_SMEM);

    agg_kernel<<<NN / 2, 256>>>(adj, data);
    recfinal_kernel<<<(NN + 31) / 32, 256, RECFINAL_SMEM>>>(data, pos, hisW, curW,
                                                            hw, cw, fw, out);
}

// round 7
// speedup vs baseline: 1.8247x; 1.1220x over previous
#include <cuda_runtime.h>

#define NN   5000
#define TT   12
#define DAYC 8
#define FF   7
#define DIMC 96
#define NV4  1250         // float4s per adj row
#define QW   313          // float4s per quarter-row scan (ceil 1250/4)
#define QNZ  64           // max 16-float-group records per quarter (mean ~6)

// Scratch (allocation-free rule: __device__ global)
__device__ float g_agg[NN * DIMC];   // [n][t*8+d], pre-scaled by 1/deg

// ---------------------------------------------------------------------------
// Kernel 1: agg[n][t*8+d] = (1/deg_n) * sum_{adj[n,i]!=0} data[t,i,d]
// 4 warps per row (quarter scans), 256 thr = 2 rows/block.
// Scan: ONE ballot per 16 floats (per-lane OR over 4 float4s); records encode
// (i4base<<16)|mask16, element masks built only on the rare hit path.
// adj streamed with __ldcs (no reuse; keep L2 for data/agg).
// ---------------------------------------------------------------------------
__global__ void __launch_bounds__(256) agg_kernel(const float* __restrict__ adj,
                                                  const float* __restrict__ data) {
    __shared__ int   s_nz[2][4][QNZ];
    __shared__ int   s_cnt[2][4];
    __shared__ float s_part[2][4][DIMC];

    const int warp = threadIdx.x >> 5;
    const int lane = threadIdx.x & 31;
    const int r    = warp >> 2;           // row slot in block (0..1)
    const int q    = warp & 3;            // quarter (0..3)
    const int row  = blockIdx.x * 2 + r;
    const unsigned lt = (1u << lane) - 1u;

    const uint4* __restrict__ arow =
        reinterpret_cast<const uint4*>(adj + (long long)row * NN);
    const int i4beg = q * QW;
    const int i4end = (i4beg + QW < NV4) ? (i4beg + QW) : NV4;

    int cnt = 0;  // record count
    for (int base = i4beg; base < i4end; base += 128) {
        uint4 v[4];
        #pragma unroll
        for (int u = 0; u < 4; u++) {
            const int i4 = base + u * 32 + lane;
            v[u] = make_uint4(0u, 0u, 0u, 0u);
            if (i4 < i4end) v[u] = __ldcs(&arow[i4]);
        }
        const unsigned any0 = v[0].x | v[0].y | v[0].z | v[0].w;
        const unsigned any1 = v[1].x | v[1].y | v[1].z | v[1].w;
        const unsigned any2 = v[2].x | v[2].y | v[2].z | v[2].w;
        const unsigned any3 = v[3].x | v[3].y | v[3].z | v[3].w;
        const unsigned tot = any0 | any1 | any2 | any3;
        const unsigned bal = __ballot_sync(0xffffffffu, tot != 0u);
        if (tot != 0u) {
            unsigned m16 = 0u;
            #pragma unroll
            for (int u = 0; u < 4; u++) {
                const unsigned m4 = (v[u].x ? 1u : 0u) | (v[u].y ? 2u : 0u)
                                  | (v[u].z ? 4u : 0u) | (v[u].w ? 8u : 0u);
                m16 |= m4 << (4 * u);
            }
            const int p = cnt + __popc(bal & lt);
            if (p < QNZ) s_nz[r][q][p] = ((base + lane) << 16) | (int)m16;
        }
        cnt += __popc(bal);
    }
    __syncwarp();
    const int nrec = (cnt < QNZ) ? cnt : QNZ;

    // gather: lane owns output cols lane, lane+32, lane+64
    const int j0 = lane, j1 = lane + 32, j2 = lane + 64;
    const int o0 = (j0 >> 3) * (NN * DAYC) + (j0 & 7);
    const int o1 = (j1 >> 3) * (NN * DAYC) + (j1 & 7);
    const int o2 = (j2 >> 3) * (NN * DAYC) + (j2 & 7);
    float a0 = 0.f, a1 = 0.f, a2 = 0.f;
    int deg = 0;
    for (int k = 0; k < nrec; k++) {
        const int rec = s_nz[r][q][k];
        const int i4l = rec >> 16;            // base + lane (float4 index)
        unsigned mk = (unsigned)(rec & 0xffff);
        deg += __popc(mk);
        do {
            const int b = __ffs(mk) - 1;
            mk &= mk - 1u;
            // element index = (i4l + (b>>2)*32)*4 + (b&3)
            const int elem = i4l * 4 + (b >> 2) * 128 + (b & 3);
            const int off = elem * DAYC;       // adj nonzeros are exactly 1.0
            a0 += __ldg(data + o0 + off);
            a1 += __ldg(data + o1 + off);
            a2 += __ldg(data + o2 + off);
        } while (mk);
    }
    s_part[r][q][j0] = a0;
    s_part[r][q][j1] = a1;
    s_part[r][q][j2] = a2;
    if (lane == 0) s_cnt[r][q] = deg;
    __syncthreads();

    if (q == 0) {
        const int tot = s_cnt[r][0] + s_cnt[r][1] + s_cnt[r][2] + s_cnt[r][3];
        const float scale = 1.0f / (float)((tot > 0) ? tot : 1);
        #pragma unroll
        for (int c3 = 0; c3 < 3; c3++) {
            const int c = lane + c3 * 32;
            g_agg[row * DIMC + c] = (s_part[r][0][c] + s_part[r][1][c]
                                   + s_part[r][2][c] + s_part[r][3][c]) * scale;
        }
    }
}

// ---------------------------------------------------------------------------
// Kernel 2 (fused rec + final), 512 threads, 32 nodes per block.
// Warps 0-7: rec (8 lanes/node, smem exchange) -> feats in shared.
// Warps 8-15: concurrently stage FW into shared, row-major pad-97.
// Shared layout 16B-aligned per sub-array (s_feat is float4-read!).
// ---------------------------------------------------------------------------
#define OFF_HISW 0
#define OFF_CURW (OFF_HISW + TT*FF*28)        // 2352
#define OFF_HW   (OFF_CURW + TT*4)            // 2400
#define OFF_CW   (OFF_HW + FF*95)             // 3065
#define OFF_RAW  ((OFF_CW + TT + 3) & ~3)     // 3080 (16B aligned)
#define OFF_AG   (OFF_RAW + 256)              // 3336
#define OFF_PREV (OFF_AG + 256)               // 3592
#define OFF_H    (OFF_PREV + 256)             // 3848
#define OFF_FEAT (OFF_H + 256)                // 4104 (16B aligned: 4104*4=16416)
#define OFF_FW   (OFF_FEAT + 32*DIMC)         // 7176
#define SMEM_FLOATS (OFF_FW + DIMC*97)        // 16488
#define RECFINAL_SMEM (SMEM_FLOATS * (int)sizeof(float))

__global__ void __launch_bounds__(512) recfinal_kernel(const float* __restrict__ data,
                                                       const float* __restrict__ pos,
                                                       const float* __restrict__ hisW,   // (12,7,28)
                                                       const float* __restrict__ curW,   // (12,1,4)
                                                       const float* __restrict__ hw,     // (7,95)
                                                       const float* __restrict__ cw,     // (1,12)
                                                       const float* __restrict__ FW,     // (96,96)
                                                       float* __restrict__ out) {
    extern __shared__ float sm[];
    float* s_hisW = sm + OFF_HISW;
    float* s_curW = sm + OFF_CURW;
    float* s_hw   = sm + OFF_HW;
    float* s_cw   = sm + OFF_CW;
    float* s_raw  = sm + OFF_RAW;
    float* s_ag   = sm + OFF_AG;
    float* s_prev = sm + OFF_PREV;
    float* s_h    = sm + OFF_H;
    float* s_feat = sm + OFF_FEAT;         // 32*96, float4-aligned
    float* s_FW   = sm + OFF_FW;           // s_FW[j*97+k] = FW[j*96+k]

    const int tid  = threadIdx.x;
    const int warp = tid >> 5;
    const int lane = tid & 31;

    const int sub = lane >> 3;             // node within warp (0..3)
    const int li  = lane & 7;              // channel role (0..7)
    const int nl  = warp * 4 + sub;        // node within block (0..31) [warps 0-7]
    const int n   = blockIdx.x * 32 + nl;
    const bool recw = (warp < 8);
    const bool act  = recw && (n < NN);
    const int  nc   = (act ? n : 0);

    // per-node input prefetch FIRST (36 independent loads in flight)
    float rawv[TT], pvv[TT], agv[TT];
    if (recw) {
        #pragma unroll
        for (int t = 0; t < TT; t++) {
            const long long base = ((long long)t * NN + nc) * DAYC + li;
            rawv[t] = __ldg(data + base);
            pvv[t]  = __ldg(pos  + base);
            agv[t]  = g_agg[nc * DIMC + t * DAYC + li];
        }
        s_prev[nl * 8 + li] = 0.f;
    }

    // all 512 threads stage the small weights
    for (int i = tid; i < TT * FF * 28; i += 512) s_hisW[i] = hisW[i];
    for (int i = tid; i < TT * 4;       i += 512) s_curW[i] = curW[i];
    for (int i = tid; i < FF * 95;      i += 512) s_hw[i]   = hw[i];
    if (tid < TT) s_cw[tid] = cw[tid];
    __syncthreads();

    if (recw) {
        // ---- rec: 12-step recurrence, feats kept in shared ----
        float accH = 0.f;                  // lane li: accH[li]
        float accC = 0.f, prevC = 0.f;     // lane 7 only
        #pragma unroll
        for (int t = 0; t < TT; t++) {
            s_raw[nl * 8 + li] = rawv[t];
            s_ag[nl * 8 + li]  = agv[t];
            __syncwarp();

            float hv;
            if (li < 7) {
                const float* Wr = s_hisW + t * FF * 28 + li * 28;
                float s = 0.f;
                #pragma unroll
                for (int j = 0; j < FF; j++) {
                    s += s_raw[nl * 8 + j]  * Wr[j];
                    s += s_ag[nl * 8 + j]   * Wr[7 + j];
                    s += s_prev[nl * 8 + j] * Wr[21 + j];
                }
                hv = fmaxf(s, 0.f) + pvv[t];
            } else {
                float c = rawv[t] * s_curW[t * 4 + 0] + agv[t] * s_curW[t * 4 + 1]
                        + prevC * s_curW[t * 4 + 3];
                hv = fmaxf(c, 0.f) + pvv[t];
            }
            s_h[nl * 8 + li] = hv;
            __syncwarp();

            if (li < 7) {
                const float* hr = s_hw + li * 95 + t * FF;
                float s = 0.f;
                #pragma unroll
                for (int j = 0; j < FF; j++) s += s_h[nl * 8 + j] * hr[j];
                accH += s;
                s_prev[nl * 8 + li] = fmaxf(accH, 0.f);
                s_feat[nl * DIMC + t * FF + li] = hv;
            } else {
                accC += hv * s_cw[t];
                prevC = fmaxf(accC, 0.f);
                s_feat[nl * DIMC + TT * FF + t] = hv;
            }
        }
    } else {
        // ---- warps 8-15: stage FW (9216 floats, coalesced both sides) ----
        const int tid2 = tid - 256;
        #pragma unroll 4
        for (int i = tid2; i < DIMC * DIMC; i += 256) {
            const int j = i / DIMC, k = i - j * DIMC;
            s_FW[j * 97 + k] = __ldg(FW + i);
        }
    }
    __syncthreads();   // feats + FW visible

    if (recw) {
        // ---- final: out[n] = relu(feat[n] @ FW^T), 4 nodes per warp ----
        const int nl0 = warp * 4;
        float acc[4][3];
        #pragma unroll
        for (int m = 0; m < 4; m++) { acc[m][0] = acc[m][1] = acc[m][2] = 0.f; }

        #pragma unroll 2
        for (int k0 = 0; k0 < DIMC; k0 += 4) {
            float4 fv[4];
            #pragma unroll
            for (int m = 0; m < 4; m++)
                fv[m] = *reinterpret_cast<const float4*>(&s_feat[(nl0 + m) * DIMC + k0]);
            #pragma unroll
            for (int kk = 0; kk < 4; kk++) {
                const int k = k0 + kk;
                const float f0 = s_FW[lane * 97 + k];
                const float f1 = s_FW[(lane + 32) * 97 + k];
                const float f2 = s_FW[(lane + 64) * 97 + k];
                #pragma unroll
                for (int m = 0; m < 4; m++) {
                    const float fvk = (kk == 0) ? fv[m].x : ((kk == 1) ? fv[m].y
                                    : ((kk == 2) ? fv[m].z : fv[m].w));
                    acc[m][0] += fvk * f0;
                    acc[m][1] += fvk * f1;
                    acc[m][2] += fvk * f2;
                }
            }
        }
        #pragma unroll
        for (int m = 0; m < 4; m++) {
            const int nn = blockIdx.x * 32 + nl0 + m;
            if (nn < NN) {
                out[nn * DIMC + lane]      = fmaxf(acc[m][0], 0.f);
                out[nn * DIMC + lane + 32] = fmaxf(acc[m][1], 0.f);
                out[nn * DIMC + lane + 64] = fmaxf(acc[m][2], 0.f);
            }
        }
    }
}

// ---------------------------------------------------------------------------
extern "C" void kernel_launch(void* const* d_in, const int* in_sizes, int n_in,
                              void* d_out, int out_size) {
    const float* adj  = (const float*)d_in[0];
    const float* data = (const float*)d_in[1];
    const float* pos  = (const float*)d_in[2];
    const float* hisW = (const float*)d_in[3];
    const float* curW = (const float*)d_in[4];
    const float* hw   = (const float*)d_in[5];
    const float* cw   = (const float*)d_in[6];
    const float* fw   = (const float*)d_in[7];
    float* out = (float*)d_out;

    cudaFuncSetAttribute(recfinal_kernel,
                         cudaFuncAttributeMaxDynamicSharedMemorySize,
                         RECFINAL_SMEM);

    agg_kernel<<<NN / 2, 256>>>(adj, data);
    recfinal_kernel<<<(NN + 31) / 32, 512, RECFINAL_SMEM>>>(data, pos, hisW, curW,
                                                            hw, cw, fw, out);
}

// round 8
// speedup vs baseline: 1.9288x; 1.0571x over previous
#include <cuda_runtime.h>

#define NN   5000
#define TT   12
#define DAYC 8
#define FF   7
#define DIMC 96
#define NV4  1250         // float4s per adj row
#define QW   313          // float4s per quarter-row scan (ceil 1250/4)
#define QNZ  64           // max 16-float-group records per quarter (mean ~6)

// Scratch (allocation-free rule: __device__ global)
__device__ float g_agg[NN * DIMC];   // [n][t*8+d], pre-scaled by 1/deg

// ---------------------------------------------------------------------------
// Kernel 1: agg[n][t*8+d] = (1/deg_n) * sum_{adj[n,i]!=0} data[t,i,d]
// 4 warps per row (quarter scans), 256 thr = 2 rows/block.
// Scan: ONE ballot per 16 floats; records (i4base<<16)|mask16. __ldcs on adj.
// ---------------------------------------------------------------------------
__global__ void __launch_bounds__(256) agg_kernel(const float* __restrict__ adj,
                                                  const float* __restrict__ data) {
    __shared__ int   s_nz[2][4][QNZ];
    __shared__ int   s_cnt[2][4];
    __shared__ float s_part[2][4][DIMC];

    const int warp = threadIdx.x >> 5;
    const int lane = threadIdx.x & 31;
    const int r    = warp >> 2;
    const int q    = warp & 3;
    const int row  = blockIdx.x * 2 + r;
    const unsigned lt = (1u << lane) - 1u;

    const uint4* __restrict__ arow =
        reinterpret_cast<const uint4*>(adj + (long long)row * NN);
    const int i4beg = q * QW;
    const int i4end = (i4beg + QW < NV4) ? (i4beg + QW) : NV4;

    int cnt = 0;
    for (int base = i4beg; base < i4end; base += 128) {
        uint4 v[4];
        #pragma unroll
        for (int u = 0; u < 4; u++) {
            const int i4 = base + u * 32 + lane;
            v[u] = make_uint4(0u, 0u, 0u, 0u);
            if (i4 < i4end) v[u] = __ldcs(&arow[i4]);
        }
        const unsigned any0 = v[0].x | v[0].y | v[0].z | v[0].w;
        const unsigned any1 = v[1].x | v[1].y | v[1].z | v[1].w;
        const unsigned any2 = v[2].x | v[2].y | v[2].z | v[2].w;
        const unsigned any3 = v[3].x | v[3].y | v[3].z | v[3].w;
        const unsigned tot = any0 | any1 | any2 | any3;
        const unsigned bal = __ballot_sync(0xffffffffu, tot != 0u);
        if (tot != 0u) {
            unsigned m16 = 0u;
            #pragma unroll
            for (int u = 0; u < 4; u++) {
                const unsigned m4 = (v[u].x ? 1u : 0u) | (v[u].y ? 2u : 0u)
                                  | (v[u].z ? 4u : 0u) | (v[u].w ? 8u : 0u);
                m16 |= m4 << (4 * u);
            }
            const int p = cnt + __popc(bal & lt);
            if (p < QNZ) s_nz[r][q][p] = ((base + lane) << 16) | (int)m16;
        }
        cnt += __popc(bal);
    }
    __syncwarp();
    const int nrec = (cnt < QNZ) ? cnt : QNZ;

    const int j0 = lane, j1 = lane + 32, j2 = lane + 64;
    const int o0 = (j0 >> 3) * (NN * DAYC) + (j0 & 7);
    const int o1 = (j1 >> 3) * (NN * DAYC) + (j1 & 7);
    const int o2 = (j2 >> 3) * (NN * DAYC) + (j2 & 7);
    float a0 = 0.f, a1 = 0.f, a2 = 0.f;
    int deg = 0;
    for (int k = 0; k < nrec; k++) {
        const int rec = s_nz[r][q][k];
        const int i4l = rec >> 16;
        unsigned mk = (unsigned)(rec & 0xffff);
        deg += __popc(mk);
        do {
            const int b = __ffs(mk) - 1;
            mk &= mk - 1u;
            const int elem = i4l * 4 + (b >> 2) * 128 + (b & 3);
            const int off = elem * DAYC;       // adj nonzeros are exactly 1.0
            a0 += __ldg(data + o0 + off);
            a1 += __ldg(data + o1 + off);
            a2 += __ldg(data + o2 + off);
        } while (mk);
    }
    s_part[r][q][j0] = a0;
    s_part[r][q][j1] = a1;
    s_part[r][q][j2] = a2;
    if (lane == 0) s_cnt[r][q] = deg;
    __syncthreads();

    if (q == 0) {
        const int tot = s_cnt[r][0] + s_cnt[r][1] + s_cnt[r][2] + s_cnt[r][3];
        const float scale = 1.0f / (float)((tot > 0) ? tot : 1);
        #pragma unroll
        for (int c3 = 0; c3 < 3; c3++) {
            const int c = lane + c3 * 32;
            g_agg[row * DIMC + c] = (s_part[r][0][c] + s_part[r][1][c]
                                   + s_part[r][2][c] + s_part[r][3][c]) * scale;
        }
    }
}

// ---------------------------------------------------------------------------
// Kernel 2 (fused rec + final), 256 threads, 16 nodes/block, grid 313
// (~2 blocks/SM resident -> cross-block phase overlap).
// Phase A: warps 0-3 rec (4 nodes each) || warps 4-7 stage FW (pad 97).
// Phase B: ALL 8 warps final GEMM, 2 nodes per warp.
// ---------------------------------------------------------------------------
#define NODES_PB 16
#define OFF_HISW 0
#define OFF_CURW (OFF_HISW + TT*FF*28)        // 2352
#define OFF_HW   (OFF_CURW + TT*4)            // 2400
#define OFF_CW   (OFF_HW + FF*95)             // 3065
#define OFF_RAW  ((OFF_CW + TT + 3) & ~3)     // 3080 (16B aligned)
#define OFF_AG   (OFF_RAW + NODES_PB*8)       // 3208
#define OFF_PREV (OFF_AG + NODES_PB*8)        // 3336
#define OFF_H    (OFF_PREV + NODES_PB*8)      // 3464
#define OFF_FEAT (OFF_H + NODES_PB*8)         // 3592 (3592*4=14368, 16B aligned)
#define OFF_FW   (OFF_FEAT + NODES_PB*DIMC)   // 5128
#define SMEM_FLOATS (OFF_FW + DIMC*97)        // 14440
#define RECFINAL_SMEM (SMEM_FLOATS * (int)sizeof(float))

__global__ void __launch_bounds__(256) recfinal_kernel(const float* __restrict__ data,
                                                       const float* __restrict__ pos,
                                                       const float* __restrict__ hisW,   // (12,7,28)
                                                       const float* __restrict__ curW,   // (12,1,4)
                                                       const float* __restrict__ hw,     // (7,95)
                                                       const float* __restrict__ cw,     // (1,12)
                                                       const float* __restrict__ FW,     // (96,96)
                                                       float* __restrict__ out) {
    extern __shared__ float sm[];
    float* s_hisW = sm + OFF_HISW;
    float* s_curW = sm + OFF_CURW;
    float* s_hw   = sm + OFF_HW;
    float* s_cw   = sm + OFF_CW;
    float* s_raw  = sm + OFF_RAW;
    float* s_ag   = sm + OFF_AG;
    float* s_prev = sm + OFF_PREV;
    float* s_h    = sm + OFF_H;
    float* s_feat = sm + OFF_FEAT;         // 16*96, float4-aligned
    float* s_FW   = sm + OFF_FW;           // s_FW[j*97+k] = FW[j*96+k]

    const int tid  = threadIdx.x;
    const int warp = tid >> 5;
    const int lane = tid & 31;

    const int sub = lane >> 3;             // node within warp (0..3)
    const int li  = lane & 7;              // channel role (0..7)
    const int nl  = warp * 4 + sub;        // node within block (0..15) [warps 0-3]
    const int n   = blockIdx.x * NODES_PB + nl;
    const bool recw = (warp < 4);
    const bool act  = recw && (n < NN);
    const int  nc   = (act ? n : 0);

    // per-node input prefetch FIRST (36 independent loads in flight)
    float rawv[TT], pvv[TT], agv[TT];
    if (recw) {
        #pragma unroll
        for (int t = 0; t < TT; t++) {
            const long long base = ((long long)t * NN + nc) * DAYC + li;
            rawv[t] = __ldg(data + base);
            pvv[t]  = __ldg(pos  + base);
            agv[t]  = g_agg[nc * DIMC + t * DAYC + li];
        }
        s_prev[nl * 8 + li] = 0.f;
    }

    // all threads stage the small weights
    for (int i = tid; i < TT * FF * 28; i += 256) s_hisW[i] = hisW[i];
    for (int i = tid; i < TT * 4;       i += 256) s_curW[i] = curW[i];
    for (int i = tid; i < FF * 95;      i += 256) s_hw[i]   = hw[i];
    if (tid < TT) s_cw[tid] = cw[tid];
    __syncthreads();

    if (recw) {
        // ---- rec: 12-step recurrence, feats kept in shared ----
        float accH = 0.f;                  // lane li: accH[li]
        float accC = 0.f, prevC = 0.f;     // lane 7 only
        #pragma unroll
        for (int t = 0; t < TT; t++) {
            s_raw[nl * 8 + li] = rawv[t];
            s_ag[nl * 8 + li]  = agv[t];
            __syncwarp();

            float hv;
            if (li < 7) {
                const float* Wr = s_hisW + t * FF * 28 + li * 28;
                float s = 0.f;
                #pragma unroll
                for (int j = 0; j < FF; j++) {
                    s += s_raw[nl * 8 + j]  * Wr[j];
                    s += s_ag[nl * 8 + j]   * Wr[7 + j];
                    s += s_prev[nl * 8 + j] * Wr[21 + j];
                }
                hv = fmaxf(s, 0.f) + pvv[t];
            } else {
                float c = rawv[t] * s_curW[t * 4 + 0] + agv[t] * s_curW[t * 4 + 1]
                        + prevC * s_curW[t * 4 + 3];
                hv = fmaxf(c, 0.f) + pvv[t];
            }
            s_h[nl * 8 + li] = hv;
            __syncwarp();

            if (li < 7) {
                const float* hr = s_hw + li * 95 + t * FF;
                float s = 0.f;
                #pragma unroll
                for (int j = 0; j < FF; j++) s += s_h[nl * 8 + j] * hr[j];
                accH += s;
                s_prev[nl * 8 + li] = fmaxf(accH, 0.f);
                s_feat[nl * DIMC + t * FF + li] = hv;
            } else {
                accC += hv * s_cw[t];
                prevC = fmaxf(accC, 0.f);
                s_feat[nl * DIMC + TT * FF + t] = hv;
            }
        }
    } else {
        // ---- warps 4-7: stage FW (9216 floats, coalesced both sides) ----
        const int tid2 = tid - 128;
        #pragma unroll 4
        for (int i = tid2; i < DIMC * DIMC; i += 128) {
            const int j = i / DIMC, k = i - j * DIMC;
            s_FW[j * 97 + k] = __ldg(FW + i);
        }
    }
    __syncthreads();   // feats + FW visible

    // ---- final: ALL 8 warps, 2 nodes per warp ----
    {
        const int nl0 = warp * 2;
        float acc[2][3];
        #pragma unroll
        for (int m = 0; m < 2; m++) { acc[m][0] = acc[m][1] = acc[m][2] = 0.f; }

        #pragma unroll 3
        for (int k0 = 0; k0 < DIMC; k0 += 4) {
            float4 fv[2];
            #pragma unroll
            for (int m = 0; m < 2; m++)
                fv[m] = *reinterpret_cast<const float4*>(&s_feat[(nl0 + m) * DIMC + k0]);
            #pragma unroll
            for (int kk = 0; kk < 4; kk++) {
                const int k = k0 + kk;
                const float f0 = s_FW[lane * 97 + k];
                const float f1 = s_FW[(lane + 32) * 97 + k];
                const float f2 = s_FW[(lane + 64) * 97 + k];
                #pragma unroll
                for (int m = 0; m < 2; m++) {
                    const float fvk = (kk == 0) ? fv[m].x : ((kk == 1) ? fv[m].y
                                    : ((kk == 2) ? fv[m].z : fv[m].w));
                    acc[m][0] += fvk * f0;
                    acc[m][1] += fvk * f1;
                    acc[m][2] += fvk * f2;
                }
            }
        }
        #pragma unroll
        for (int m = 0; m < 2; m++) {
            const int nn = blockIdx.x * NODES_PB + nl0 + m;
            if (nn < NN) {
                out[nn * DIMC + lane]      = fmaxf(acc[m][0], 0.f);
                out[nn * DIMC + lane + 32] = fmaxf(acc[m][1], 0.f);
                out[nn * DIMC + lane + 64] = fmaxf(acc[m][2], 0.f);
            }
        }
    }
}

// ---------------------------------------------------------------------------
extern "C" void kernel_launch(void* const* d_in, const int* in_sizes, int n_in,
                              void* d_out, int out_size) {
    const float* adj  = (const float*)d_in[0];
    const float* data = (const float*)d_in[1];
    const float* pos  = (const float*)d_in[2];
    const float* hisW = (const float*)d_in[3];
    const float* curW = (const float*)d_in[4];
    const float* hw   = (const float*)d_in[5];
    const float* cw   = (const float*)d_in[6];
    const float* fw   = (const float*)d_in[7];
    float* out = (float*)d_out;

    cudaFuncSetAttribute(recfinal_kernel,
                         cudaFuncAttributeMaxDynamicSharedMemorySize,
                         RECFINAL_SMEM);

    agg_kernel<<<NN / 2, 256>>>(adj, data);
    recfinal_kernel<<<(NN + NODES_PB - 1) / NODES_PB, 256, RECFINAL_SMEM>>>(
        data, pos, hisW, curW, hw, cw, fw, out);
}